// round 5
// baseline (speedup 1.0000x reference)
#include <cuda_runtime.h>
#include <cooperative_groups.h>
#include <math.h>

namespace cg = cooperative_groups;

#define EPS 1e-8f
// B=64, S=64, I=64, O=64, N=1024, M=64, H=256, 4H=1024, P=268
// 8-CTA cluster handles 2 batches (32 clusters, 512 thr/CTA, ~98KB smem -> occ 2).
// rank = blockIdx.x & 7; bown = rank>>2 (batch whose memory this CTA owns),
// q = rank&3 (n-quarter [256q, 256q+256)).
// GEMMs are cluster-wide for BOTH batches: rank owns h-dims [32r,32r+32) (gate cols
// {qb*256+32r..+32}), head cols [34r,34r+34) (30 for rank 7), out cols [8r,8r+8).

struct SMem {
    float  mem[64 * 256];     // own batch's memory quarter, [m][nl] (64 KB)
    float4 part[1024];        // GEMM / addressing partials (16 KB), scalar-reused
    float  wr[256], ww[256];
    float  t1[256], t2[256];
    float  h[2][2][256];      // [buf][batch][H]
    float  c[2][32];          // [batch][own 32 dims]
    float  xr[2][128];
    float  gates[2][128];     // own col slice: [batch][qb*32+jl]
    float  p[272];            // full head output for OWN batch
    float  kr[64], kw[64], e[64], a[64];
    float  rpart[64];
    float  rrecv[8][64];
    float  rvec[2][64];
    float  scal[16];          // 0..5 read head, 6=|kr|, 7=|kw|, 8..13 write head
    float  qhalo[4];          // [qr at next-nbr nl0, qr at prev-nbr nl255, qw..., qw...]
    float  wh_r[2], wh_w[2];  // prev-step w halos: [next-nbr nl0, prev-nbr nl255]
    float2 xsum[4];           // per-quarter exp-sum partials (own batch)
    float2 xsp[4];            // per-quarter sharpen-sum partials
    float2 red[16];
};

__device__ __forceinline__ float sigmoidf_(float x) { return 1.f / (1.f + expf(-x)); }
__device__ __forceinline__ float softplusf_(float x) { return fmaxf(x, 0.f) + log1pf(expf(-fabsf(x))); }

__device__ __forceinline__ float2 blockReduceSum2(float2 v, float2* red) {
#pragma unroll
    for (int o = 16; o; o >>= 1) {
        v.x += __shfl_xor_sync(0xffffffffu, v.x, o);
        v.y += __shfl_xor_sync(0xffffffffu, v.y, o);
    }
    int w = threadIdx.x >> 5;
    if ((threadIdx.x & 31) == 0) red[w] = v;
    __syncthreads();
    if (threadIdx.x < 32) {
        v = (threadIdx.x < 16) ? red[threadIdx.x] : make_float2(0.f, 0.f);
#pragma unroll
        for (int o = 8; o; o >>= 1) {
            v.x += __shfl_xor_sync(0xffffffffu, v.x, o);
            v.y += __shfl_xor_sync(0xffffffffu, v.y, o);
        }
        if (threadIdx.x == 0) red[0] = v;
    }
    __syncthreads();
    v = red[0];
    __syncthreads();
    return v;
}

__global__ void __launch_bounds__(512, 2) __cluster_dims__(8, 1, 1)
ntm_kernel(const float* __restrict__ x,       // (64,64,64)
           const float* __restrict__ Wx,      // (128,1024)
           const float* __restrict__ Wh,      // (256,1024)
           const float* __restrict__ b_lstm,  // (1024)
           const float* __restrict__ W_head,  // (256,268)
           const float* __restrict__ b_head,  // (268)
           const float* __restrict__ W_out,   // (320,64)
           const float* __restrict__ b_out,   // (64)
           float* __restrict__ out)           // (64,64,64)
{
    extern __shared__ char smraw[];
    SMem* s = (SMem*)smraw;
    cg::cluster_group cl = cg::this_cluster();

    const int rank = blockIdx.x & 7;
    const int clid = blockIdx.x >> 3;
    const int t    = threadIdx.x;
    const int bown = rank >> 2;
    const int q    = rank & 3;

    SMem* P[8];
#pragma unroll
    for (int i = 0; i < 8; ++i) P[i] = (SMem*)cl.map_shared_rank(smraw, i);
    SMem* Pqnext = P[bown * 4 + ((q + 1) & 3)];
    SMem* Pqprev = P[bown * 4 + ((q + 3) & 3)];

    float*  partf = (float*)s->part;
    float4* mem4  = (float4*)s->mem;

    // ---- init ----
    {
        float4 iv = make_float4(0.01f, 0.01f, 0.01f, 0.01f);
#pragma unroll
        for (int i = 0; i < 8; ++i) mem4[i * 512 + t] = iv;   // 4096 float4
        if (t < 256) { float w0 = (q == 0 && t == 0) ? 1.f : 0.f; s->wr[t] = w0; s->ww[t] = w0; }
        if (t < 512) { ((float*)s->h)[t] = 0.f; ((float*)s->h)[512 + t] = 0.f; }
        if (t < 64)  { ((float*)s->c)[t] = 0.f; }
        if (t < 128) { ((float*)s->rvec)[t] = 0.f; }
        if (t == 0) {
            float hv = (q == 3) ? 1.f : 0.f;   // next nbr's nl0 is global n=0 only for q==3
            s->wh_r[0] = hv; s->wh_w[0] = hv;
            s->wh_r[1] = 0.f; s->wh_w[1] = 0.f;
        }
    }
    cl.sync();

    for (int step = 0; step < 64; ++step) {
        const int prv = step & 1, cur = prv ^ 1;
        const float* hpA = s->h[prv][0];
        const float* hpB = s->h[prv][1];

        // ---- phase 1: xr[bat] = [x_t(bat), rvec(bat)] ----
        if (t < 256) {
            int bat = t >> 7, idx = t & 127;
            int bg = clid * 2 + bat;
            s->xr[bat][idx] = (idx < 64) ? x[((bg << 6) + step) * 64 + idx]
                                         : s->rvec[bat][idx - 64];
        }
        __syncthreads();

        // ---- phase 2: gates, own 128 cols x 2 batches (32 float4 cols, split-K 16) ----
        {
            int o = t & 31, ch = t >> 5;           // ch 0..15, rows [24ch, 24ch+24)
            int qb = o >> 3, qw = o & 7;
            int col4 = qb * 64 + rank * 8 + qw;
            const float4* wx4 = (const float4*)Wx;
            const float4* wh4 = (const float4*)Wh;
            float4 aA = make_float4(0.f, 0.f, 0.f, 0.f);
            float4 aB = make_float4(0.f, 0.f, 0.f, 0.f);
            int r0 = ch * 24;
#pragma unroll 8
            for (int rr = r0; rr < r0 + 24; ++rr) {
                float4 w = (rr < 128) ? wx4[rr * 256 + col4] : wh4[(rr - 128) * 256 + col4];
                float vA = (rr < 128) ? s->xr[0][rr] : hpA[rr - 128];
                float vB = (rr < 128) ? s->xr[1][rr] : hpB[rr - 128];
                aA.x += vA * w.x; aA.y += vA * w.y; aA.z += vA * w.z; aA.w += vA * w.w;
                aB.x += vB * w.x; aB.y += vB * w.y; aB.z += vB * w.z; aB.w += vB * w.w;
            }
            s->part[t] = aA;
            s->part[512 + t] = aB;
        }
        __syncthreads();
        if (t < 64) {
            int bat = t >> 5, o = t & 31;
            int qb = o >> 3, qw = o & 7;
            int col4 = qb * 64 + rank * 8 + qw;
            float4 acc = ((const float4*)b_lstm)[col4];
#pragma unroll
            for (int ch = 0; ch < 16; ++ch) {
                float4 pc = s->part[bat * 512 + ch * 32 + o];
                acc.x += pc.x; acc.y += pc.y; acc.z += pc.z; acc.w += pc.w;
            }
            ((float4*)s->gates[bat])[qb * 8 + qw] = acc;
        }
        __syncthreads();

        // ---- phase 3: LSTM pointwise on own 32 h-dims x 2 batches; broadcast h ----
        if (t < 64) {
            int bat = t >> 5, jl = t & 31;
            float ig = s->gates[bat][jl],      fg = s->gates[bat][32 + jl],
                  gg = s->gates[bat][64 + jl], og = s->gates[bat][96 + jl];
            float cc = sigmoidf_(fg) * s->c[bat][jl] + sigmoidf_(ig) * tanhf(gg);
            s->c[bat][jl] = cc;
            float hv = sigmoidf_(og) * tanhf(cc);
            int gj = rank * 32 + jl;
#pragma unroll
            for (int i = 0; i < 8; ++i) P[i]->h[cur][bat][gj] = hv;
        }
        cl.sync();   // S1: full new h in all 8 CTAs

        // ---- phase 4: head GEMM, own 34 cols x 2 batches; scatter p to batch owners ----
        const float* hnA = s->h[cur][0];
        const float* hnB = s->h[cur][1];
        const int cr = (rank < 7) ? 34 : 30;
        if (t < 238) {
            int j = t % 34, ch = t / 34;          // ch 0..6
            float aA = 0.f, aB = 0.f;
            if (j < cr) {
                int col = 34 * rank + j;
                int k0 = ch * 37, k1 = (ch == 6) ? 256 : k0 + 37;
                for (int k = k0; k < k1; ++k) {
                    float w = W_head[k * 268 + col];
                    aA += hnA[k] * w;
                    aB += hnB[k] * w;
                }
            }
            partf[t * 2] = aA;
            partf[t * 2 + 1] = aB;
        } else if (t >= 448) {
            s->rpart[t - 448] = 0.f;              // zero r accumulator
        }
        __syncthreads();
        if (t < 68) {
            int j = t >> 1, bat = t & 1;
            if (j < cr) {
                int col = 34 * rank + j;
                float v = b_head[col];
#pragma unroll
                for (int ch = 0; ch < 7; ++ch) v += partf[(ch * 34 + j) * 2 + bat];
#pragma unroll
                for (int i = 0; i < 4; ++i) P[bat * 4 + i]->p[col] = v;
            }
        }
        cl.sync();   // S2: full p for own batch in each CTA

        // ---- phase 5: parse heads (locally, duplicated within batch group) ----
        if (t < 64) s->kr[t] = tanhf(s->p[t]);
        else if (t < 128) s->kw[t - 64] = tanhf(s->p[70 + t - 64]);
        else if (t < 192) s->e[t - 128] = sigmoidf_(s->p[140 + (t - 128)]);
        else if (t < 256) s->a[t - 192] = s->p[204 + (t - 192)];
        else if (t == 256) {
            s->scal[0] = softplusf_(s->p[64]);
            s->scal[1] = sigmoidf_(s->p[65]);
            float a0 = s->p[66], a1 = s->p[67], a2 = s->p[68];
            float mx = fmaxf(a0, fmaxf(a1, a2));
            float e0 = expf(a0 - mx), e1 = expf(a1 - mx), e2 = expf(a2 - mx);
            float sm = e0 + e1 + e2;
            s->scal[2] = e0 / sm; s->scal[3] = e1 / sm; s->scal[4] = e2 / sm;
            s->scal[5] = 1.f + softplusf_(s->p[69]);
        } else if (t == 288) {
            s->scal[8] = softplusf_(s->p[134]);
            s->scal[9] = sigmoidf_(s->p[135]);
            float a0 = s->p[136], a1 = s->p[137], a2 = s->p[138];
            float mx = fmaxf(a0, fmaxf(a1, a2));
            float e0 = expf(a0 - mx), e1 = expf(a1 - mx), e2 = expf(a2 - mx);
            float sm = e0 + e1 + e2;
            s->scal[10] = e0 / sm; s->scal[11] = e1 / sm; s->scal[12] = e2 / sm;
            s->scal[13] = 1.f + softplusf_(s->p[139]);
        }
        __syncthreads();
        if (t < 32) {
            float v = s->kr[t] * s->kr[t] + s->kr[t + 32] * s->kr[t + 32];
#pragma unroll
            for (int o = 16; o; o >>= 1) v += __shfl_xor_sync(0xffffffffu, v, o);
            if (t == 0) s->scal[6] = sqrtf(v);
        } else if (t < 64) {
            int l = t - 32;
            float v = s->kw[l] * s->kw[l] + s->kw[l + 32] * s->kw[l + 32];
#pragma unroll
            for (int o = 16; o; o >>= 1) v += __shfl_xor_sync(0xffffffffu, v, o);
            if (l == 0) s->scal[7] = sqrtf(v);
        }
        __syncthreads();

        // ---- phase 6: addressing over own 256 n-rows (mem in SMEM) ----
        const int nl = t & 255, mh = t >> 8;
        {
            float dr = 0.f, dw = 0.f, nn = 0.f;
            int m0 = mh * 32;
#pragma unroll 8
            for (int m = m0; m < m0 + 32; ++m) {
                float v = s->mem[m * 256 + nl];
                dr += s->kr[m] * v;
                dw += s->kw[m] * v;
                nn += v * v;
            }
            s->part[t] = make_float4(dr, dw, nn, 0.f);
        }
        __syncthreads();
        const bool lead = (t < 256);
        float qr = 0.f, qww = 0.f, er = 0.f, ew = 0.f;
        if (lead) {
            float4 p0 = s->part[t], p1 = s->part[t + 256];
            float dr = p0.x + p1.x, dw = p0.y + p1.y, nn = p0.z + p1.z;
            float nrm = sqrtf(nn);
            qr  = s->scal[0] * (dr / (s->scal[6] * nrm + EPS));
            qww = s->scal[8] * (dw / (s->scal[7] * nrm + EPS));
            if (nl == 0)   { Pqprev->qhalo[0] = qr; Pqprev->qhalo[2] = qww; }
            if (nl == 255) { Pqnext->qhalo[1] = qr; Pqnext->qhalo[3] = qww; }
            er = expf(qr);     // |q| <= beta (softplus-bounded): overflow-safe
            ew = expf(qww);
        }
        float2 lsum = blockReduceSum2(make_float2(er, ew), s->red);
        if (t == 0) {
#pragma unroll
            for (int i = 0; i < 4; ++i) P[bown * 4 + i]->xsum[q] = lsum;
        }
        cl.sync();   // S3: exp-sum partials + boundary q in batch group
        const float gsr = s->xsum[0].x + s->xsum[1].x + s->xsum[2].x + s->xsum[3].x;
        const float gsw = s->xsum[0].y + s->xsum[1].y + s->xsum[2].y + s->xsum[3].y;
        const float g_r = s->scal[1], g_w = s->scal[9];
        if (lead) {
            float wgr = g_r * (er / gsr) + (1.f - g_r) * s->wr[nl];
            float wgw = g_w * (ew / gsw) + (1.f - g_w) * s->ww[nl];
            s->t1[nl] = wgr;
            s->t2[nl] = wgw;
        }
        __syncthreads();
        float wpr = 0.f, wpw = 0.f;
        if (lead) {
            float t1p = (nl == 255) ? (g_r * (expf(s->qhalo[0]) / gsr) + (1.f - g_r) * s->wh_r[0]) : s->t1[nl + 1];
            float t1m = (nl == 0)   ? (g_r * (expf(s->qhalo[1]) / gsr) + (1.f - g_r) * s->wh_r[1]) : s->t1[nl - 1];
            float t2p = (nl == 255) ? (g_w * (expf(s->qhalo[2]) / gsw) + (1.f - g_w) * s->wh_w[0]) : s->t2[nl + 1];
            float t2m = (nl == 0)   ? (g_w * (expf(s->qhalo[3]) / gsw) + (1.f - g_w) * s->wh_w[1]) : s->t2[nl - 1];
            float wsr = s->scal[2]  * t1p + s->scal[3]  * s->t1[nl] + s->scal[4]  * t1m;
            float wsw = s->scal[10] * t2p + s->scal[11] * s->t2[nl] + s->scal[12] * t2m;
            wpr = (wsr > 0.f) ? expf(s->scal[5]  * logf(wsr)) : 0.f;
            wpw = (wsw > 0.f) ? expf(s->scal[13] * logf(wsw)) : 0.f;
        }
        float2 lsp = blockReduceSum2(make_float2(wpr, wpw), s->red);
        if (t == 0) {
#pragma unroll
            for (int i = 0; i < 4; ++i) P[bown * 4 + i]->xsp[q] = lsp;
        }
        cl.sync();   // S4: sharpen-sum partials in batch group
        if (lead) {
            float gpr = s->xsp[0].x + s->xsp[1].x + s->xsp[2].x + s->xsp[3].x;
            float gpw = s->xsp[0].y + s->xsp[1].y + s->xsp[2].y + s->xsp[3].y;
            float wrv = wpr / (gpr + EPS);
            float wwv = wpw / (gpw + EPS);
            s->wr[nl] = wrv;
            s->ww[nl] = wwv;
            // push new boundary w to neighbors' prev-w halos (ordered by S5)
            if (nl == 0)   { Pqprev->wh_r[0] = wrv; Pqprev->wh_w[0] = wwv; }
            if (nl == 255) { Pqnext->wh_r[1] = wrv; Pqnext->wh_w[1] = wwv; }
        }
        __syncthreads();

        // ---- phase 7: fused read (old mem) + erase/add update ----
        {
            int n4 = t & 63, mch = t >> 6;    // 8 m-rows per thread
            float4 wr4 = ((const float4*)s->wr)[n4];
            float4 ww4 = ((const float4*)s->ww)[n4];
#pragma unroll 4
            for (int mi = 0; mi < 8; ++mi) {
                int m = mch * 8 + mi;
                float em = s->e[m], am = s->a[m];
                float4 v = mem4[m * 64 + n4];
                float rp = wr4.x * v.x + wr4.y * v.y + wr4.z * v.z + wr4.w * v.w;
                v.x = v.x * (1.f - ww4.x * em) + ww4.x * am;
                v.y = v.y * (1.f - ww4.y * em) + ww4.y * am;
                v.z = v.z * (1.f - ww4.z * em) + ww4.z * am;
                v.w = v.w * (1.f - ww4.w * em) + ww4.w * am;
                mem4[m * 64 + n4] = v;
#pragma unroll
                for (int o = 16; o; o >>= 1) rp += __shfl_xor_sync(0xffffffffu, rp, o);
                if ((t & 31) == 0) atomicAdd(&s->rpart[m], rp);
            }
        }
        __syncthreads();
        if (t < 64) {   // broadcast r partial to all 8 CTAs
            float v = s->rpart[t];
#pragma unroll
            for (int i = 0; i < 8; ++i) P[i]->rrecv[rank][t] = v;
        }
        cl.sync();   // S5: r partials everywhere (+ w halos ordered)
        if (t < 128) {
            int bat = t >> 6, i = t & 63;
            s->rvec[bat][i] = s->rrecv[bat * 4][i] + s->rrecv[bat * 4 + 1][i]
                            + s->rrecv[bat * 4 + 2][i] + s->rrecv[bat * 4 + 3][i];
        }
        __syncthreads();

        // ---- phase 8: out GEMM, own 8 cols x 2 batches ----
        {
            int oi = t & 15, ch = t >> 4;     // 32 chunks x 10 rows
            int bat = oi >> 3, jc = oi & 7;
            int col = 8 * rank + jc;
            const float* hh = bat ? hnB : hnA;
            float acc = 0.f;
            int r0 = ch * 10;
#pragma unroll
            for (int rr = r0; rr < r0 + 10; ++rr) {
                float v = (rr < 256) ? hh[rr] : s->rvec[bat][rr - 256];
                acc += v * W_out[rr * 64 + col];
            }
            partf[t] = acc;
        }
        __syncthreads();
        if (t < 16) {
            int bat = t >> 3, jc = t & 7;
            int col = 8 * rank + jc;
            float acc = b_out[col];
#pragma unroll
            for (int ch = 0; ch < 32; ++ch) acc += partf[t + 16 * ch];
            int bg = clid * 2 + bat;
            out[((bg << 6) + step) * 64 + col] = acc;
        }
        __syncthreads();
    }
}

extern "C" void kernel_launch(void* const* d_in, const int* in_sizes, int n_in,
                              void* d_out, int out_size) {
    const float* x      = (const float*)d_in[0];
    const float* Wx     = (const float*)d_in[1];
    const float* Wh     = (const float*)d_in[2];
    const float* b_lstm = (const float*)d_in[3];
    const float* W_head = (const float*)d_in[4];
    const float* b_head = (const float*)d_in[5];
    const float* W_out  = (const float*)d_in[6];
    const float* b_out  = (const float*)d_in[7];
    float* out = (float*)d_out;

    size_t smem = sizeof(SMem);
    cudaFuncSetAttribute(ntm_kernel, cudaFuncAttributeMaxDynamicSharedMemorySize, (int)smem);
    ntm_kernel<<<256, 512, smem>>>(x, Wx, Wh, b_lstm, W_head, b_head, W_out, b_out, out);
}

// round 6
// speedup vs baseline: 1.1974x; 1.1974x over previous
#include <cuda_runtime.h>
#include <cooperative_groups.h>
#include <math.h>

namespace cg = cooperative_groups;

#define EPS 1e-8f
typedef unsigned long long u64;
// B=64, S=64, I=64, O=64, N=1024, M=64, H=256, 4H=1024, P=268
// 4-CTA cluster handles 2 batches (round-4 structure). Ranks {0,1} own batch A's
// memory n-halves, {2,3} batch B's. GEMMs cluster-wide for BOTH batches via
// packed f32x2 math: one weight load drives both batches' FMAs in packed pairs.

struct SMem {
    float  mem[64 * 512];     // own batch's memory half, [m][nl] (128 KB)
    float4 part[2048];        // GEMM / addressing partials (32 KB), reused
    float  wr[512], ww[512];
    float  t1[512], t2[512];
    float2 vh[640];           // [0,128): xr pairs; [128,384): h bank0; [384,640): h bank1
    float2 h2c[256];          // current-step h pairs {hA, hB}
    float  c[2][64];          // [batch][own 64 dims]
    float  gates[2][256];     // own col slice per batch
    float  p[272];            // full head output for OWN batch
    float2 krw[64];           // {kr[m], kw[m]}
    float  e[64], a[64];
    float  rpart[64];
    float  rrecv[4][64];
    float2 rvec2[64];         // {rA, rB}
    float  scal[16];          // 0..5 read head, 6=|kr|, 7=|kw|, 8..13 write head
    float  qhalo[4];
    float  wh_r[2], wh_w[2];
    float  xch[4];
    float2 red[32];
};

__device__ __forceinline__ float sigmoidf_(float x) { return 1.f / (1.f + expf(-x)); }
__device__ __forceinline__ float softplusf_(float x) { return fmaxf(x, 0.f) + log1pf(expf(-fabsf(x))); }

__device__ __forceinline__ u64 pk2(float a, float b) {
    u64 r; asm("mov.b64 %0, {%1, %2};" : "=l"(r) : "f"(a), "f"(b)); return r;
}
__device__ __forceinline__ float2 up2(u64 v) {
    float2 r; asm("mov.b64 {%0, %1}, %2;" : "=f"(r.x), "=f"(r.y) : "l"(v)); return r;
}
__device__ __forceinline__ void fma2(u64& d, u64 a, u64 b) {
    asm("fma.rn.f32x2 %0, %1, %2, %0;" : "+l"(d) : "l"(a), "l"(b));
}
__device__ __forceinline__ u64 fma2n(u64 a, u64 b, u64 c) {
    u64 d; asm("fma.rn.f32x2 %0, %1, %2, %3;" : "=l"(d) : "l"(a), "l"(b), "l"(c)); return d;
}
__device__ __forceinline__ u64 mul2(u64 a, u64 b) {
    u64 d; asm("mul.rn.f32x2 %0, %1, %2;" : "=l"(d) : "l"(a), "l"(b)); return d;
}
__device__ __forceinline__ u64 add2(u64 a, u64 b) {
    u64 d; asm("add.rn.f32x2 %0, %1, %2;" : "=l"(d) : "l"(a), "l"(b)); return d;
}

__device__ __forceinline__ float2 blockReduceSum2(float2 v, float2* red) {
#pragma unroll
    for (int o = 16; o; o >>= 1) {
        v.x += __shfl_xor_sync(0xffffffffu, v.x, o);
        v.y += __shfl_xor_sync(0xffffffffu, v.y, o);
    }
    int w = threadIdx.x >> 5;
    if ((threadIdx.x & 31) == 0) red[w] = v;
    __syncthreads();
    if (threadIdx.x < 32) {
        v = red[threadIdx.x];
#pragma unroll
        for (int o = 16; o; o >>= 1) {
            v.x += __shfl_xor_sync(0xffffffffu, v.x, o);
            v.y += __shfl_xor_sync(0xffffffffu, v.y, o);
        }
        if (threadIdx.x == 0) red[0] = v;
    }
    __syncthreads();
    v = red[0];
    __syncthreads();
    return v;
}

__global__ void __launch_bounds__(1024, 1) __cluster_dims__(4, 1, 1)
ntm_kernel(const float* __restrict__ x,       // (64,64,64)
           const float* __restrict__ Wx,      // (128,1024)
           const float* __restrict__ Wh,      // (256,1024)
           const float* __restrict__ b_lstm,  // (1024)
           const float* __restrict__ W_head,  // (256,268)
           const float* __restrict__ b_head,  // (268)
           const float* __restrict__ W_out,   // (320,64)
           const float* __restrict__ b_out,   // (64)
           float* __restrict__ out)           // (64,64,64)
{
    extern __shared__ char smraw[];
    SMem* s = (SMem*)smraw;
    cg::cluster_group cl = cg::this_cluster();

    const int rank = (int)cl.block_rank();    // 0..3
    const int clid = blockIdx.x >> 2;         // 0..31
    const int t    = threadIdx.x;

    SMem* P0 = (SMem*)cl.map_shared_rank(smraw, 0);
    SMem* P1 = (SMem*)cl.map_shared_rank(smraw, 1);
    SMem* P2 = (SMem*)cl.map_shared_rank(smraw, 2);
    SMem* P3 = (SMem*)cl.map_shared_rank(smraw, 3);
    SMem* PP[4] = {P0, P1, P2, P3};
    SMem* pp = (SMem*)cl.map_shared_rank(smraw, rank ^ 1);   // pair peer

    float2*     part2 = (float2*)s->part;
    ulonglong2* partq = (ulonglong2*)s->part;
    float4*     mem4  = (float4*)s->mem;
    ulonglong2* memq  = (ulonglong2*)s->mem;

    const int bgA = clid * 2, bgB = clid * 2 + 1;

    // ---- init ----
    {
        float4 iv = make_float4(0.01f, 0.01f, 0.01f, 0.01f);
#pragma unroll
        for (int i = 0; i < 8; ++i) mem4[i * 1024 + t] = iv;
        if (t < 512) { float w0 = ((rank & 1) == 0 && t == 0) ? 1.f : 0.f; s->wr[t] = w0; s->ww[t] = w0; }
        if (t < 640) s->vh[t] = make_float2(0.f, 0.f);
        if (t < 256) s->h2c[t] = make_float2(0.f, 0.f);
        if (t < 128) ((float*)s->c)[t] = 0.f;
        if (t < 64)  s->rvec2[t] = make_float2(0.f, 0.f);
        if (t == 0) {
            float hv = (rank & 1) ? 1.f : 0.f;   // peer nl0 is global n=0 for odd ranks
            s->wh_r[0] = hv; s->wh_w[0] = hv;
            s->wh_r[1] = 0.f; s->wh_w[1] = 0.f;
        }
    }
    cl.sync();

    for (int step = 0; step < 64; ++step) {
        const int prv = step & 1, cur = prv ^ 1;

        // ---- phase 1: vh[0:128) = {x_t, r} pairs for both batches ----
        if (t < 64) {
            s->vh[t] = make_float2(x[((bgA << 6) + step) * 64 + t],
                                   x[((bgB << 6) + step) * 64 + t]);
        } else if (t < 128) {
            s->vh[t] = s->rvec2[t - 64];
        }
        __syncthreads();

        // ---- phase 2: gates, own 256 cols x 2 batches, packed f32x2 ----
        {
            int qi = t & 63, qb = qi >> 4, qw = qi & 15;
            int col4 = qb * 64 + rank * 16 + qw;
            int ch = t >> 6;                 // 0..15, rows [24ch, 24ch+24)
            const ulonglong2* wx2 = (const ulonglong2*)Wx;   // row stride 256
            const ulonglong2* wh2 = (const ulonglong2*)Wh;
            u64 aA01 = 0ull, aA23 = 0ull, aB01 = 0ull, aB23 = 0ull;
            int r0 = ch * 24;
#pragma unroll 8
            for (int rr = r0; rr < r0 + 24; ++rr) {
                ulonglong2 w2 = (rr < 128) ? wx2[rr * 256 + col4]
                                           : wh2[(rr - 128) * 256 + col4];
                float2 vv = s->vh[(rr < 128) ? rr : rr + prv * 256];
                u64 vA2 = pk2(vv.x, vv.x), vB2 = pk2(vv.y, vv.y);
                fma2(aA01, w2.x, vA2); fma2(aA23, w2.y, vA2);
                fma2(aB01, w2.x, vB2); fma2(aB23, w2.y, vB2);
            }
            ulonglong2 sa; sa.x = aA01; sa.y = aA23;
            ulonglong2 sb; sb.x = aB01; sb.y = aB23;
            partq[t] = sa;
            partq[1024 + t] = sb;
        }
        __syncthreads();
        if (t < 128) {
            int bat = t >> 6, qi = t & 63;
            int qb = qi >> 4, qw = qi & 15;
            int col4 = qb * 64 + rank * 16 + qw;
            ulonglong2 bb = ((const ulonglong2*)b_lstm)[col4];
            u64 a01 = bb.x, a23 = bb.y;
#pragma unroll
            for (int ch = 0; ch < 16; ++ch) {
                ulonglong2 pc = partq[bat * 1024 + ch * 64 + qi];
                a01 = add2(a01, pc.x); a23 = add2(a23, pc.y);
            }
            ulonglong2 g; g.x = a01; g.y = a23;
            ((ulonglong2*)s->gates[bat])[qi] = g;
        }
        __syncthreads();

        // ---- phase 3: LSTM pointwise; publish h pairs to all 4 CTAs ----
        if (t < 128) {
            int bat = t >> 6, jl = t & 63;
            float ig = s->gates[bat][jl],       fg = s->gates[bat][64 + jl],
                  gg = s->gates[bat][128 + jl], og = s->gates[bat][192 + jl];
            float cc = sigmoidf_(fg) * s->c[bat][jl] + sigmoidf_(ig) * tanhf(gg);
            s->c[bat][jl] = cc;
            float hv = sigmoidf_(og) * tanhf(cc);
            int gj = rank * 64 + jl;
#pragma unroll
            for (int i = 0; i < 4; ++i) {
                ((float*)&PP[i]->vh[128 + cur * 256 + gj])[bat] = hv;
                ((float*)&PP[i]->h2c[gj])[bat] = hv;
            }
        }
        cl.sync();   // S1: full new h pairs in all 4 CTAs

        // ---- phase 4: head GEMM, own 68 cols x both batches packed ----
        const int cr = (rank < 3) ? 68 : 64;
        if (t < 952) {
            int ch = t / 68, j = t - ch * 68;       // ch 0..13
            u64 acc = 0ull;
            if (j < cr) {
                int col = 68 * rank + j;
                int k0 = (ch * 128) / 7, k1 = ((ch + 1) * 128) / 7;
                for (int k = k0; k < k1; ++k) {
                    float w = W_head[k * 268 + col];
                    u64 hv = *(const u64*)(s->h2c + k);
                    fma2(acc, hv, pk2(w, w));
                }
            }
            part2[t] = up2(acc);
        } else if (t >= 960) {
            s->rpart[t - 960] = 0.f;                // zero r accumulator
        }
        __syncthreads();
        if (t < 68 && t < cr) {
            int col = 68 * rank + t;
            float2 acc = make_float2(0.f, 0.f);
#pragma unroll
            for (int ch = 0; ch < 14; ++ch) {
                float2 pv = part2[ch * 68 + t];
                acc.x += pv.x; acc.y += pv.y;
            }
            float bh = b_head[col];
            acc.x += bh; acc.y += bh;
            P0->p[col] = acc.x; P1->p[col] = acc.x;
            P2->p[col] = acc.y; P3->p[col] = acc.y;
        }
        cl.sync();   // S2: full p for own batch in each CTA

        // ---- phase 5: parse heads ----
        if (t < 64) s->krw[t].x = tanhf(s->p[t]);
        else if (t < 128) s->krw[t - 64].y = tanhf(s->p[70 + t - 64]);
        else if (t < 192) s->e[t - 128] = sigmoidf_(s->p[140 + (t - 128)]);
        else if (t < 256) s->a[t - 192] = s->p[204 + (t - 192)];
        else if (t == 256) {
            s->scal[0] = softplusf_(s->p[64]);
            s->scal[1] = sigmoidf_(s->p[65]);
            float a0 = s->p[66], a1 = s->p[67], a2 = s->p[68];
            float mx = fmaxf(a0, fmaxf(a1, a2));
            float e0 = expf(a0 - mx), e1 = expf(a1 - mx), e2 = expf(a2 - mx);
            float sm = e0 + e1 + e2;
            s->scal[2] = e0 / sm; s->scal[3] = e1 / sm; s->scal[4] = e2 / sm;
            s->scal[5] = 1.f + softplusf_(s->p[69]);
        } else if (t == 288) {
            s->scal[8] = softplusf_(s->p[134]);
            s->scal[9] = sigmoidf_(s->p[135]);
            float a0 = s->p[136], a1 = s->p[137], a2 = s->p[138];
            float mx = fmaxf(a0, fmaxf(a1, a2));
            float e0 = expf(a0 - mx), e1 = expf(a1 - mx), e2 = expf(a2 - mx);
            float sm = e0 + e1 + e2;
            s->scal[10] = e0 / sm; s->scal[11] = e1 / sm; s->scal[12] = e2 / sm;
            s->scal[13] = 1.f + softplusf_(s->p[139]);
        }
        __syncthreads();
        if (t < 32) {
            float kv = s->krw[t].x, kv2 = s->krw[t + 32].x;
            float v = kv * kv + kv2 * kv2;
#pragma unroll
            for (int o = 16; o; o >>= 1) v += __shfl_xor_sync(0xffffffffu, v, o);
            if (t == 0) s->scal[6] = sqrtf(v);
        } else if (t < 64) {
            int l = t - 32;
            float kv = s->krw[l].y, kv2 = s->krw[l + 32].y;
            float v = kv * kv + kv2 * kv2;
#pragma unroll
            for (int o = 16; o; o >>= 1) v += __shfl_xor_sync(0xffffffffu, v, o);
            if (l == 0) s->scal[7] = sqrtf(v);
        }
        __syncthreads();

        // ---- phase 6: addressing over own 512 n-rows, packed {dr,dw} ----
        const int nl = t & 511, mh = t >> 9;
        {
            u64 drw = 0ull;
            float nn = 0.f;
            int m0 = mh * 32;
#pragma unroll 8
            for (int m = m0; m < m0 + 32; ++m) {
                float v = s->mem[m * 512 + nl];
                u64 kv = *(const u64*)(s->krw + m);
                fma2(drw, kv, pk2(v, v));
                nn += v * v;
            }
            float2 d = up2(drw);
            s->part[t] = make_float4(d.x, d.y, nn, 0.f);
        }
        __syncthreads();
        const bool lead = (t < 512);
        float qr = 0.f, qw = 0.f, er = 0.f, ew = 0.f;
        if (lead) {
            float4 p0 = s->part[t], p1 = s->part[t + 512];
            float dr = p0.x + p1.x, dw = p0.y + p1.y, nn = p0.z + p1.z;
            float nrm = sqrtf(nn);
            qr = s->scal[0] * (dr / (s->scal[6] * nrm + EPS));
            qw = s->scal[8] * (dw / (s->scal[7] * nrm + EPS));
            if (nl == 0)   { pp->qhalo[0] = qr; pp->qhalo[2] = qw; }
            if (nl == 511) { pp->qhalo[1] = qr; pp->qhalo[3] = qw; }
            er = expf(qr);          // |q| <= beta (softplus-bounded): overflow-safe
            ew = expf(qw);
        }
        float2 lsum = blockReduceSum2(make_float2(er, ew), s->red);
        if (t == 0) { pp->xch[0] = lsum.x; pp->xch[1] = lsum.y; }
        cl.sync();   // S3: exp-sums + boundary q exchanged within pair
        const float gsr = lsum.x + s->xch[0];
        const float gsw = lsum.y + s->xch[1];
        const float g_r = s->scal[1], g_w = s->scal[9];
        if (lead) {
            float wgr = g_r * (er / gsr) + (1.f - g_r) * s->wr[nl];
            float wgw = g_w * (ew / gsw) + (1.f - g_w) * s->ww[nl];
            s->t1[nl] = wgr;
            s->t2[nl] = wgw;
        }
        __syncthreads();
        float wpr = 0.f, wpw = 0.f;
        if (lead) {
            float t1p = (nl == 511) ? (g_r * (expf(s->qhalo[0]) / gsr) + (1.f - g_r) * s->wh_r[0]) : s->t1[nl + 1];
            float t1m = (nl == 0)   ? (g_r * (expf(s->qhalo[1]) / gsr) + (1.f - g_r) * s->wh_r[1]) : s->t1[nl - 1];
            float t2p = (nl == 511) ? (g_w * (expf(s->qhalo[2]) / gsw) + (1.f - g_w) * s->wh_w[0]) : s->t2[nl + 1];
            float t2m = (nl == 0)   ? (g_w * (expf(s->qhalo[3]) / gsw) + (1.f - g_w) * s->wh_w[1]) : s->t2[nl - 1];
            float wsr = s->scal[2]  * t1p + s->scal[3]  * s->t1[nl] + s->scal[4]  * t1m;
            float wsw = s->scal[10] * t2p + s->scal[11] * s->t2[nl] + s->scal[12] * t2m;
            wpr = (wsr > 0.f) ? expf(s->scal[5]  * logf(wsr)) : 0.f;
            wpw = (wsw > 0.f) ? expf(s->scal[13] * logf(wsw)) : 0.f;
        }
        float2 lsp = blockReduceSum2(make_float2(wpr, wpw), s->red);
        if (t == 0) { pp->xch[2] = lsp.x; pp->xch[3] = lsp.y; }
        cl.sync();   // S4: sharpen sums exchanged within pair
        if (lead) {
            float wrv = wpr / ((lsp.x + s->xch[2]) + EPS);
            float wwv = wpw / ((lsp.y + s->xch[3]) + EPS);
            s->wr[nl] = wrv;
            s->ww[nl] = wwv;
            // push new boundary w to peer's prev-w halos for next step (ordered by S5)
            if (nl == 0)   { pp->wh_r[0] = wrv; pp->wh_w[0] = wwv; }
            if (nl == 511) { pp->wh_r[1] = wrv; pp->wh_w[1] = wwv; }
        }
        __syncthreads();

        // ---- phase 7: fused read (old mem) + erase/add update, packed ----
        {
            int n4 = t & 127, mch = t >> 7;
            ulonglong2 wr2 = ((const ulonglong2*)s->wr)[n4];
            ulonglong2 ww2 = ((const ulonglong2*)s->ww)[n4];
            const u64 one2 = pk2(1.f, 1.f);
#pragma unroll 4
            for (int mi = 0; mi < 8; ++mi) {
                int m = mch * 8 + mi;
                float em = s->e[m], am = s->a[m];
                u64 nem2 = pk2(-em, -em), am2 = pk2(am, am);
                ulonglong2 v2 = memq[m * 128 + n4];
                u64 rp2 = 0ull;
                fma2(rp2, wr2.x, v2.x); fma2(rp2, wr2.y, v2.y);
                float2 rr = up2(rp2);
                float rp = rr.x + rr.y;
                u64 f01 = fma2n(ww2.x, nem2, one2);
                u64 f23 = fma2n(ww2.y, nem2, one2);
                u64 g01 = mul2(ww2.x, am2);
                u64 g23 = mul2(ww2.y, am2);
                v2.x = fma2n(v2.x, f01, g01);
                v2.y = fma2n(v2.y, f23, g23);
                memq[m * 128 + n4] = v2;
#pragma unroll
                for (int o = 16; o; o >>= 1) rp += __shfl_xor_sync(0xffffffffu, rp, o);
                if ((t & 31) == 0) atomicAdd(&s->rpart[m], rp);
            }
        }
        __syncthreads();
        if (t < 64) {   // broadcast r partial to all 4 CTAs
            float v = s->rpart[t];
#pragma unroll
            for (int i = 0; i < 4; ++i) PP[i]->rrecv[rank][t] = v;
        }
        // ---- phase 8a (pre-S5): out GEMM h-part, overlaps the r exchange ----
        {
            int jc = t & 15, ch = t >> 4;      // 64 chunks x 4 rows
            int col = rank * 16 + jc;
            u64 acc = 0ull;
            int r0 = ch * 4;
#pragma unroll
            for (int rr = r0; rr < r0 + 4; ++rr) {
                float w = W_out[rr * 64 + col];
                u64 hv = *(const u64*)(s->h2c + rr);
                fma2(acc, hv, pk2(w, w));
            }
            part2[t] = up2(acc);
        }
        cl.sync();   // S5: r partials everywhere (+ w halos ordered)
        if (t < 64) {
            s->rvec2[t] = make_float2(s->rrecv[0][t] + s->rrecv[1][t],
                                      s->rrecv[2][t] + s->rrecv[3][t]);
        }
        __syncthreads();
        // ---- phase 8b: r-part + reduce + write ----
        {
            int jc = t & 15, ch = t >> 4;      // 64 rows: 256+ch
            int col = rank * 16 + jc;
            float w = W_out[(256 + ch) * 64 + col];
            float2 rv = s->rvec2[ch];
            float2 pv = part2[t];
            pv.x += rv.x * w; pv.y += rv.y * w;
            part2[t] = pv;
        }
        __syncthreads();
        if (t < 128) {
            int jc = t & 15, g = t >> 4;       // 8 groups of 8 chunks
            float2 acc = make_float2(0.f, 0.f);
#pragma unroll
            for (int k = 0; k < 8; ++k) {
                float2 pv = part2[(g * 8 + k) * 16 + jc];
                acc.x += pv.x; acc.y += pv.y;
            }
            part2[1024 + t] = acc;
        }
        __syncthreads();
        if (t < 16) {
            int col = rank * 16 + t;
            float b = b_out[col];
            float2 acc = make_float2(b, b);
#pragma unroll
            for (int g = 0; g < 8; ++g) {
                float2 pv = part2[1024 + g * 16 + t];
                acc.x += pv.x; acc.y += pv.y;
            }
            out[((bgA << 6) + step) * 64 + col] = acc.x;
            out[((bgB << 6) + step) * 64 + col] = acc.y;
        }
        __syncthreads();
    }
}

extern "C" void kernel_launch(void* const* d_in, const int* in_sizes, int n_in,
                              void* d_out, int out_size) {
    const float* x      = (const float*)d_in[0];
    const float* Wx     = (const float*)d_in[1];
    const float* Wh     = (const float*)d_in[2];
    const float* b_lstm = (const float*)d_in[3];
    const float* W_head = (const float*)d_in[4];
    const float* b_head = (const float*)d_in[5];
    const float* W_out  = (const float*)d_in[6];
    const float* b_out  = (const float*)d_in[7];
    float* out = (float*)d_out;

    size_t smem = sizeof(SMem);
    cudaFuncSetAttribute(ntm_kernel, cudaFuncAttributeMaxDynamicSharedMemorySize, (int)smem);
    ntm_kernel<<<128, 1024, smem>>>(x, Wx, Wh, b_lstm, W_head, b_head, W_out, b_out, out);
}